// round 11
// baseline (speedup 1.0000x reference)
#include <cuda_runtime.h>
#include <cuda_fp16.h>
#include <cstdint>

#define N_DIM 512

// ---------------- scratch ----------------
__device__ __half g_Bh[128 * 512];             // fp16 W: rows 0..63 = Ws, 64..127 = Wo
__device__ __half g_P[(size_t)100000 * 128];   // fp16 P (25.6MB): [0..63]=s, [64..127]=o

// ---------------- smem geometry (4-stage, M=256, K-chunk=32) ----------------
#define A_STAGE_B 32768                        // 256 rows x 128B (fp32 x32, XOR-swizzled, no pad)
#define B_ROW_H   48                           // 32 data halfs + 16 pad
#define B_STAGE_B (128 * B_ROW_H * 2)          // 12288
#define B_OFF     (4 * A_STAGE_B)              // 131072
#define SMEM_BYTES (4 * A_STAGE_B + 4 * B_STAGE_B)   // 180224

// ---------------- helpers ----------------
__device__ __forceinline__ uint32_t smem_u32(const void* p) {
    uint32_t a;
    asm("{ .reg .u64 t; cvta.to.shared.u64 t, %1; cvt.u32.u64 %0, t; }" : "=r"(a) : "l"(p));
    return a;
}
__device__ __forceinline__ void cp16(uint32_t saddr, const void* g) {
    asm volatile("cp.async.cg.shared.global [%0], [%1], 16;" :: "r"(saddr), "l"(g));
}
__device__ __forceinline__ void cp_commit() {
    asm volatile("cp.async.commit_group;" ::: "memory");
}
template <int N>
__device__ __forceinline__ void cp_wait() {
    asm volatile("cp.async.wait_group %0;" :: "n"(N) : "memory");
}
__device__ __forceinline__ void hmma16816(float d[4], const uint32_t a[4], uint32_t b0, uint32_t b1) {
    asm volatile("mma.sync.aligned.m16n8k16.row.col.f32.f16.f16.f32 "
                 "{%0,%1,%2,%3},{%4,%5,%6,%7},{%8,%9},{%0,%1,%2,%3};"
                 : "+f"(d[0]), "+f"(d[1]), "+f"(d[2]), "+f"(d[3])
                 : "r"(a[0]), "r"(a[1]), "r"(a[2]), "r"(a[3]), "r"(b0), "r"(b1));
}
__device__ __forceinline__ uint32_t pack_h2(float x, float y) {
    __half2 h = __floats2half2_rn(x, y);
    return *reinterpret_cast<uint32_t*>(&h);
}
// A swizzle: within a 128B row r, 16B-granule byte col c -> c ^ (((r&1)<<6)|((r&6)<<3))
__device__ __forceinline__ uint32_t axor(int row) {
    return ((row & 1) << 6) | ((row & 6) << 3);
}

// ---------------- kernel 0: W fp32 -> fp16, reorder to [128][512] ----------------
__global__ __launch_bounds__(128) void prep_kernel(const float* __restrict__ W) {
    int i = (blockIdx.x * 128 + threadIdx.x) * 2;
    if (i >= 128 * 512) return;
    int n = i >> 9, k = i & 511;
    const float* src = (n < 64) ? (W + n * 1024 + k) : (W + (n - 64) * 1024 + 512 + k);
    float2 v = *(const float2*)src;
    *(__half2*)&g_Bh[i] = __floats2half2_rn(v.x, v.y);
}

// ---------------- kernel 1: persistent P = emb @ B^T, 4-stage K=32 cp.async ----------------
__global__ __launch_bounds__(512, 1) void gemm_kernel(const float* __restrict__ emb,
                                                      int n_nodes, int ntiles, int grid) {
    extern __shared__ char smem[];
    const uint32_t sb = smem_u32(smem);
    const int tid = threadIdx.x;
    const int lane = tid & 31;
    const int wid = tid >> 5;
    const int wm = wid & 7;     // 8 M-tiles of 32 (CTA M=256)
    const int wn = wid >> 3;    // 2 N-tiles of 64
    const int bid = blockIdx.x;

    const int ntiles_mine = (ntiles - bid + grid - 1) / grid;
    const int gtot = ntiles_mine * 16;          // 16 K-chunks of 32 per tile

    // producer: global chunk g -> (tile, kchunk c = g&15), into slot g%4
    auto ISSUE = [&](int g) {
        if (g >= gtot) return;
        const int tile = bid + (g >> 4) * grid;
        const int c = g & 15;
        const int ctaM = tile * 256;
        const uint32_t aBase = sb + (g & 3) * A_STAGE_B;
        const uint32_t bBase = sb + B_OFF + (g & 3) * B_STAGE_B;
        #pragma unroll
        for (int i = 0; i < 4; i++) {           // A: 2048 granules of 16B
            int gr = tid + i * 512;
            int row = gr >> 3, col = gr & 7;
            int ar = ctaM + row;
            if (ar >= n_nodes) ar = n_nodes - 1;
            cp16(aBase + row * 128 + (((uint32_t)col * 16) ^ axor(row)),
                 emb + (size_t)ar * N_DIM + c * 32 + col * 4);
        }
        {                                        // B: 512 granules (L2-resident g_Bh)
            int row = tid >> 2, col = tid & 3;
            cp16(bBase + row * (B_ROW_H * 2) + col * 16,
                 g_Bh + row * N_DIM + c * 32 + col * 8);
        }
    };

    float acc[2][8][4];
    #pragma unroll
    for (int i = 0; i < 2; i++)
        #pragma unroll
        for (int j = 0; j < 8; j++)
            #pragma unroll
            for (int k = 0; k < 4; k++) acc[i][j][k] = 0.0f;

    ISSUE(0); cp_commit();
    ISSUE(1); cp_commit();
    ISSUE(2); cp_commit();

    const int q = lane & 3;
    const int octr = lane >> 2;
    const uint32_t axm = axor(octr);   // r0 & 7 == octr for all consumed rows

    for (int g = 0; g < gtot; g++) {
        // pending entering here: {g, g+1, g+2} -> wait<2> forces chunk g complete
        cp_wait<2>();
        __syncthreads();          // stage-g visible; all warps done with g-1 -> slot (g+3)%4 free
        ISSUE(g + 3);
        cp_commit();              // unconditional: keeps positional group count

        const uint32_t aOff = (g & 3) * A_STAGE_B;
        const uint32_t bOff = B_OFF + (g & 3) * B_STAGE_B;

        #pragma unroll
        for (int ks = 0; ks < 2; ks++) {
            // A frags: sigma k-permuted LDS.128 of swizzled fp32 + cvt to fp16
            uint32_t afr[2][4];
            #pragma unroll
            for (int mt = 0; mt < 2; mt++) {
                const int r0 = wm * 32 + mt * 16 + octr;
                const uint32_t cx = ((uint32_t)(ks * 64 + q * 16)) ^ axm;
                const float4 v0 = *(const float4*)(smem + aOff + r0 * 128 + cx);
                const float4 v1 = *(const float4*)(smem + aOff + (r0 + 8) * 128 + cx);
                afr[mt][0] = pack_h2(v0.x, v0.y);
                afr[mt][1] = pack_h2(v1.x, v1.y);
                afr[mt][2] = pack_h2(v0.z, v0.w);
                afr[mt][3] = pack_h2(v1.z, v1.w);
            }
            // B frags: one LDS.64 per n8 frag, same sigma
            uint2 bfr[8];
            #pragma unroll
            for (int nf = 0; nf < 8; nf++) {
                const int n = wn * 64 + nf * 8 + octr;
                bfr[nf] = *(const uint2*)(smem + bOff + n * (B_ROW_H * 2) + ks * 32 + q * 8);
            }
            #pragma unroll
            for (int mt = 0; mt < 2; mt++)
                #pragma unroll
                for (int nf = 0; nf < 8; nf++)
                    hmma16816(acc[mt][nf], afr[mt], bfr[nf].x, bfr[nf].y);
        }

        if ((g & 15) == 15) {
            // epilogue: fp16 pack + store (4 lanes x half2 = 16B coalesced)
            const int ctaM = (bid + (g >> 4) * grid) * 256;
            #pragma unroll
            for (int mt = 0; mt < 2; mt++) {
                const int r0 = ctaM + wm * 32 + mt * 16 + (lane >> 2);
                const int r1 = r0 + 8;
                #pragma unroll
                for (int nf = 0; nf < 8; nf++) {
                    const int col = wn * 64 + nf * 8 + (lane & 3) * 2;
                    if (r0 < n_nodes)
                        *(uint32_t*)&g_P[(size_t)r0 * 128 + col] = pack_h2(acc[mt][nf][0], acc[mt][nf][1]);
                    if (r1 < n_nodes)
                        *(uint32_t*)&g_P[(size_t)r1 * 128 + col] = pack_h2(acc[mt][nf][2], acc[mt][nf][3]);
                    acc[mt][nf][0] = acc[mt][nf][1] = acc[mt][nf][2] = acc[mt][nf][3] = 0.0f;
                }
            }
        }
    }
}

// ---------------- kernel 2: per-triple gather-combine, 2 triples/thread, fp16 P ----------------
__global__ __launch_bounds__(256) void gather_kernel(const int* __restrict__ triples,
                                                     const float* __restrict__ b,
                                                     float* __restrict__ out, int n) {
    int t = blockIdx.x * blockDim.x + threadIdx.x;
    int half = (n + 1) >> 1;
    if (t >= half) return;
    int t2 = t + half;
    bool has2 = t2 < n;

    int s1 = triples[t],  r1 = triples[n + t],  o1 = triples[2 * n + t];
    int s2 = 0, r2 = 0, o2 = 0;
    if (has2) { s2 = triples[t2]; r2 = triples[n + t2]; o2 = triples[2 * n + t2]; }

    __half a1 = __ldg(&g_P[(size_t)s1 * 128 + r1]);
    __half c1 = __ldg(&g_P[(size_t)o1 * 128 + 64 + r1]);
    __half a2 = __float2half(0.f), c2 = __float2half(0.f);
    if (has2) {
        a2 = __ldg(&g_P[(size_t)s2 * 128 + r2]);
        c2 = __ldg(&g_P[(size_t)o2 * 128 + 64 + r2]);
    }

    out[t] = __half2float(a1) + __half2float(c1) + __ldg(&b[r1]);
    if (has2) out[t2] = __half2float(a2) + __half2float(c2) + __ldg(&b[r2]);
}

extern "C" void kernel_launch(void* const* d_in, const int* in_sizes, int n_in,
                              void* d_out, int out_size)
{
    const float* emb     = (const float*)d_in[0];
    const float* W       = (const float*)d_in[1];
    const float* b       = (const float*)d_in[2];
    const int*   triples = (const int*)d_in[3];
    float*       out     = (float*)d_out;

    int n_nodes = in_sizes[0] / N_DIM;   // 100000
    int n_tr    = in_sizes[3] / 3;       // 200000
    int ntiles  = (n_nodes + 255) / 256;

    static int nsm = 0;
    if (nsm == 0) {
        cudaDeviceGetAttribute(&nsm, cudaDevAttrMultiProcessorCount, 0);
        cudaFuncSetAttribute(gemm_kernel, cudaFuncAttributeMaxDynamicSharedMemorySize, SMEM_BYTES);
    }
    int grid = (ntiles < nsm) ? ntiles : nsm;

    prep_kernel<<<256, 128>>>(W);
    gemm_kernel<<<grid, 512, SMEM_BYTES>>>(emb, n_nodes, ntiles, grid);
    gather_kernel<<<((n_tr + 1) / 2 + 255) / 256, 256>>>(triples, b, out, n_tr);
}